// round 17
// baseline (speedup 1.0000x reference)
#include <cuda_runtime.h>
#include <cstdint>

#define FULLMASK 0xffffffffu
#define KB 8
#define KH 8
#define KR 128
#define KC 128
#define KDQ 16
#define L2E 1.4426950408889634f

__device__ float g_score[KB * KH * KR * KC];

__device__ __forceinline__ float ex2(float x) {
    float r;
    asm("ex2.approx.f32 %0, %1;" : "=f"(r) : "f"(x));
    return r;
}
__device__ __forceinline__ uint32_t tf32r(float f) {
    uint32_t u;
    asm("cvt.rna.tf32.f32 %0, %1;" : "=r"(u) : "f"(f));
    return u;
}
__device__ __forceinline__ void mma8(float& c0, float& c1, float& c2, float& c3,
                                     uint32_t a0, uint32_t a1, uint32_t a2,
                                     uint32_t a3, uint32_t b0, uint32_t b1) {
    asm volatile(
        "mma.sync.aligned.m16n8k8.row.col.f32.tf32.tf32.f32 "
        "{%0,%1,%2,%3}, {%4,%5,%6,%7}, {%8,%9}, {%0,%1,%2,%3};"
        : "+f"(c0), "+f"(c1), "+f"(c2), "+f"(c3)
        : "r"(a0), "r"(a1), "r"(a2), "r"(a3), "r"(b0), "r"(b1));
}
__device__ __forceinline__ void gbar(int grp) {
    asm volatile("bar.sync %0, 128;" :: "r"(grp + 1) : "memory");
}

// ---------------------------------------------------------------------------
// Kernel 1 (unchanged from round 16): grid 256, 256 thr, smem 111104
// ---------------------------------------------------------------------------
__global__ __launch_bounds__(256) void k1_score(const float* __restrict__ q,
                                                const float* __restrict__ ks,
                                                const float* __restrict__ ka) {
    extern __shared__ float sm[];
    float* ksT   = sm;            // [16][132]
    float* kaT   = sm + 2112;     // [16][132]
    float* qrow  = sm + 4224;     // [128*16]
    float* pbuf4 = sm + 6272;     // [8][4][128]
    float* dpa   = sm + 10368;    // [128][136]

    const int bh      = blockIdx.x >> 2;
    const int quarter = blockIdx.x & 3;
    const int tid = threadIdx.x;
    const float* qb  = q  + bh * 2048;
    const float* ksb = ks + bh * 2048;
    const float* kab = ka + bh * 2048;

    for (int i = tid; i < 2048; i += 256) {
        int srow = i >> 4, e = i & 15;
        ksT[e * 132 + srow] = ksb[i];
        kaT[e * 132 + srow] = kab[i];
        qrow[i] = qb[i];
    }
    __syncthreads();

    const int w = tid >> 5, l = tid & 31;

    for (int k = 0; k < 16; ++k) {
        int r = w * 16 + k;
        float qr[16];
#pragma unroll
        for (int j = 0; j < 4; ++j) {
            float4 v4 = *(const float4*)&qrow[r * 16 + 4 * j];
            qr[4*j] = v4.x; qr[4*j+1] = v4.y; qr[4*j+2] = v4.z; qr[4*j+3] = v4.w;
        }
        float a0 = 0.f, a1 = 0.f, a2 = 0.f, a3 = 0.f;
#pragma unroll
        for (int e = 0; e < 16; ++e) {
            float4 kk = *(const float4*)&kaT[e * 132 + 4 * l];
            a0 = fmaf(qr[e], kk.x, a0); a1 = fmaf(qr[e], kk.y, a1);
            a2 = fmaf(qr[e], kk.z, a2); a3 = fmaf(qr[e], kk.w, a3);
        }
        float4 o;
        o.x = fmaxf(a0 * 0.25f, 0.f); o.y = fmaxf(a1 * 0.25f, 0.f);
        o.z = fmaxf(a2 * 0.25f, 0.f); o.w = fmaxf(a3 * 0.25f, 0.f);
        *(float4*)&dpa[r * 136 + 4 * l] = o;
    }
    __syncthreads();

    for (int k = 0; k < 4; ++k) {
        int r = quarter * 32 + w * 4 + k;
        float qr[16];
#pragma unroll
        for (int j = 0; j < 4; ++j) {
            float4 v4 = *(const float4*)&qrow[r * 16 + 4 * j];
            qr[4*j] = v4.x; qr[4*j+1] = v4.y; qr[4*j+2] = v4.z; qr[4*j+3] = v4.w;
        }
        float a0 = 0.f, a1 = 0.f, a2 = 0.f, a3 = 0.f;
#pragma unroll
        for (int e = 0; e < 16; ++e) {
            float4 kk = *(const float4*)&ksT[e * 132 + 4 * l];
            a0 = fmaf(qr[e], kk.x, a0); a1 = fmaf(qr[e], kk.y, a1);
            a2 = fmaf(qr[e], kk.z, a2); a3 = fmaf(qr[e], kk.w, a3);
        }
        float x0 = a0 * 0.25f, x1 = a1 * 0.25f, x2 = a2 * 0.25f, x3 = a3 * 0.25f;
        a0 = x0 * normcdff(x0); a1 = x1 * normcdff(x1);
        a2 = x2 * normcdff(x2); a3 = x3 * normcdff(x3);
        float mx = fmaxf(fmaxf(a0, a1), fmaxf(a2, a3));
#pragma unroll
        for (int o = 16; o; o >>= 1) mx = fmaxf(mx, __shfl_xor_sync(FULLMASK, mx, o));
        float p0 = __expf(a0 - mx), p1 = __expf(a1 - mx);
        float p2 = __expf(a2 - mx), p3 = __expf(a3 - mx);
        float ssum = p0 + p1 + p2 + p3;
#pragma unroll
        for (int o = 16; o; o >>= 1) ssum += __shfl_xor_sync(FULLMASK, ssum, o);
        float inv = 1.f / ssum;
        *(float4*)&pbuf4[w * 512 + k * 128 + 4 * l] =
            make_float4(p0*inv, p1*inv, p2*inv, p3*inv);
    }
    __syncwarp();

    float acc[16];
#pragma unroll
    for (int i = 0; i < 16; ++i) acc[i] = 0.f;
    const float* pb = &pbuf4[w * 512];
#pragma unroll 2
    for (int s = 0; s < 128; ++s) {
        float4 dv = *(const float4*)&dpa[s * 136 + 4 * l];
        float pk0 = pb[s], pk1 = pb[128 + s];
        float pk2 = pb[256 + s], pk3 = pb[384 + s];
        acc[0]  = fmaf(pk0, dv.x, acc[0]);  acc[1]  = fmaf(pk0, dv.y, acc[1]);
        acc[2]  = fmaf(pk0, dv.z, acc[2]);  acc[3]  = fmaf(pk0, dv.w, acc[3]);
        acc[4]  = fmaf(pk1, dv.x, acc[4]);  acc[5]  = fmaf(pk1, dv.y, acc[5]);
        acc[6]  = fmaf(pk1, dv.z, acc[6]);  acc[7]  = fmaf(pk1, dv.w, acc[7]);
        acc[8]  = fmaf(pk2, dv.x, acc[8]);  acc[9]  = fmaf(pk2, dv.y, acc[9]);
        acc[10] = fmaf(pk2, dv.z, acc[10]); acc[11] = fmaf(pk2, dv.w, acc[11]);
        acc[12] = fmaf(pk3, dv.x, acc[12]); acc[13] = fmaf(pk3, dv.y, acc[13]);
        acc[14] = fmaf(pk3, dv.z, acc[14]); acc[15] = fmaf(pk3, dv.w, acc[15]);
    }
#pragma unroll
    for (int k = 0; k < 4; ++k) {
        int r = quarter * 32 + w * 4 + k;
        *(float4*)&g_score[(bh * 128 + r) * 128 + 4 * l] =
            make_float4(acc[4*k] * 0.25f, acc[4*k+1] * 0.25f,
                        acc[4*k+2] * 0.25f, acc[4*k+3] * 0.25f);
    }
}

// ---------------------------------------------------------------------------
// Kernel 2: 4 CTAs/SM — aeT aliases the dead tile region (extra group
// barriers), edge partials in persistent registers, single-buffer rows.
// grid 1024, 256 thr; dynamic smem 42688 B, regs capped at 64.
// ---------------------------------------------------------------------------
__global__ __launch_bounds__(256, 4) void k2_main(
    const float* __restrict__ cost_mat,
    const float* __restrict__ mix1_w, const float* __restrict__ mix1_b,
    const float* __restrict__ Waa,
    const float* __restrict__ mix2_w, const float* __restrict__ mix2_b,
    const float* __restrict__ edge_w, const float* __restrict__ edge_b,
    const float* __restrict__ ln_g,  const float* __restrict__ ln_b,
    const float* __restrict__ v, float* __restrict__ out) {
    extern __shared__ float sm[];
    float* w1a_all  = sm;            // [8][16]
    float* w1b_all  = sm + 128;
    float* b1s_all  = sm + 256;
    float* w2s_all  = sm + 384;
    float* ews_all  = sm + 512;
    float* costrow  = sm + 640;
    float* lng      = sm + 768;
    float* lnb      = sm + 896;
    float* b2_all   = sm + 1024;     // [8], pad to 16

    const int tid = threadIdx.x;
    const int grp = tid >> 7;        // group 0/1 -> heads 4grp..4grp+3
    const int gw  = (tid >> 5) & 3;  // warp within group
    const int l   = tid & 31;
    const int c   = tid & 127;       // row owned within group
    const int g   = l >> 2, tq = l & 3;
    const int rot4 = 4 * ((tq + (g >> 1)) & 3);

    float* gb       = sm + 1040 + grp * 4816;
    float* waa      = gb;            // [16][20] tf32(Waa*L2E), padded
    float* scrow    = gb + 320;      // [128]
    float* mixedrow = gb + 448;      // [128]
    float* Msm      = gb + 576;      // [4], pad 8
    float* ms1r_f   = gb + 584;      // [128][16] tf32 ms1, paired-e chunks
    float* ms1T_f   = gb + 2632;     // [16][136] tf32 ms1^T, natural order
    float* aeT      = gb + 584;      // [16][130] ALIASES tiles (dead then)

    const int br = blockIdx.x;
    const int b = br >> 7, r = br & 127;

    if (tid < 128) {
        int h0 = tid >> 4, e0 = tid & 15;
        w1a_all[tid] = mix1_w[h0 * 32 + e0];
        w1b_all[tid] = mix1_w[h0 * 32 + 16 + e0];
        b1s_all[tid] = mix1_b[tid];
        w2s_all[tid] = mix2_w[tid];
        ews_all[tid] = edge_w[tid];
        costrow[tid] = cost_mat[br * 128 + tid];
        lng[tid] = ln_g[tid];
        lnb[tid] = ln_b[tid];
    }
    if (tid < 8) b2_all[tid] = mix2_b[tid];
    __syncthreads();

    float eacc[4] = {0.f, 0.f, 0.f, 0.f};   // persistent edge partials

    for (int hh = 0; hh < 4; ++hh) {
        const int h = grp * 4 + hh;

        // ---- P1: waa reload (pre-tf32); ms1 row c -> tiles; mixed; max ----
        waa[(c >> 4) * 20 + (c & 15)] =
            __uint_as_float(tf32r(Waa[h * 256 + c] * L2E));
        waa[((c + 128) >> 4) * 20 + (c & 15)] =
            __uint_as_float(tf32r(Waa[h * 256 + c + 128] * L2E));

        float sc = g_score[((b * KH + h) * KR + r) * KC + c];
        float co = costrow[c];
        scrow[c] = sc;
        float m[16];
        {
            const float4* wa4 = (const float4*)&w1a_all[h * 16];
            const float4* wb4 = (const float4*)&w1b_all[h * 16];
            const float4* bi4 = (const float4*)&b1s_all[h * 16];
#pragma unroll
            for (int j = 0; j < 4; ++j) {
                float4 a = wa4[j], bq = wb4[j], bi = bi4[j];
                m[4*j+0] = fmaxf(fmaf(sc, a.x, fmaf(co, bq.x, bi.x)), 0.f);
                m[4*j+1] = fmaxf(fmaf(sc, a.y, fmaf(co, bq.y, bi.y)), 0.f);
                m[4*j+2] = fmaxf(fmaf(sc, a.z, fmaf(co, bq.z, bi.z)), 0.f);
                m[4*j+3] = fmaxf(fmaf(sc, a.w, fmaf(co, bq.w, bi.w)), 0.f);
            }
        }
        {
            float rm = m[0];
#pragma unroll
            for (int e = 1; e < 16; ++e) rm = fmaxf(rm, m[e]);
#pragma unroll
            for (int o = 16; o; o >>= 1) rm = fmaxf(rm, __shfl_xor_sync(FULLMASK, rm, o));
            if (l == 0) Msm[gw] = rm;
        }
#pragma unroll
        for (int t = 0; t < 4; ++t) {
            float4 ch;
            ch.x = __uint_as_float(tf32r(m[2*t]));
            ch.y = __uint_as_float(tf32r(m[2*t + 1]));
            ch.z = __uint_as_float(tf32r(m[2*t + 8]));
            ch.w = __uint_as_float(tf32r(m[2*t + 9]));
            *(float4*)&ms1r_f[c * 16 + 4 * ((t + (c >> 1)) & 3)] = ch;
        }
#pragma unroll
        for (int e = 0; e < 16; ++e)
            ms1T_f[e * 136 + c] = __uint_as_float(tf32r(m[e]));
        {
            float mx = b2_all[h];
            const float4* w24 = (const float4*)&w2s_all[h * 16];
#pragma unroll
            for (int j = 0; j < 4; ++j) {
                float4 ww = w24[j];
                mx = fmaf(m[4*j],   ww.x, mx); mx = fmaf(m[4*j+1], ww.y, mx);
                mx = fmaf(m[4*j+2], ww.z, mx); mx = fmaf(m[4*j+3], ww.w, mx);
            }
            mixedrow[c] = mx;
        }
        gbar(grp);   // B1

        const float Mmax = fmaxf(fmaxf(Msm[0], Msm[1]), fmaxf(Msm[2], Msm[3]));

        // ---- P2a: t-GEMM for both row-blocks (t stays in registers) ----
        uint32_t wf[8];
        wf[0] = __float_as_uint(waa[(2*tq)   * 20 + g]);
        wf[1] = __float_as_uint(waa[(2*tq+1) * 20 + g]);
        wf[2] = __float_as_uint(waa[(8+2*tq) * 20 + g]);
        wf[3] = __float_as_uint(waa[(9+2*tq) * 20 + g]);
        wf[4] = __float_as_uint(waa[(2*tq)   * 20 + g + 8]);
        wf[5] = __float_as_uint(waa[(2*tq+1) * 20 + g + 8]);
        wf[6] = __float_as_uint(waa[(8+2*tq) * 20 + g + 8]);
        wf[7] = __float_as_uint(waa[(9+2*tq) * 20 + g + 8]);

        float mub[2][2];
        uint32_t daf[2][4], dbf[2][4];
#pragma unroll
        for (int rb = 0; rb < 2; ++rb) {
            const int R = gw * 32 + rb * 16;
            float4 tA = *(const float4*)&ms1r_f[(R + g)     * 16 + rot4];
            float4 tB = *(const float4*)&ms1r_f[(R + g + 8) * 16 + rot4];
            float tc0 = 0.f, tc1 = 0.f, tc2 = 0.f, tc3 = 0.f;
            float tc4 = 0.f, tc5 = 0.f, tc6 = 0.f, tc7 = 0.f;
            uint32_t ax = __float_as_uint(tA.x), bx = __float_as_uint(tB.x);
            uint32_t ay = __float_as_uint(tA.y), by = __float_as_uint(tB.y);
            uint32_t az = __float_as_uint(tA.z), bz = __float_as_uint(tB.z);
            uint32_t aw = __float_as_uint(tA.w), bw = __float_as_uint(tB.w);
            mma8(tc0, tc1, tc2, tc3, ax, bx, ay, by, wf[0], wf[1]);
            mma8(tc0, tc1, tc2, tc3, az, bz, aw, bw, wf[2], wf[3]);
            mma8(tc4, tc5, tc6, tc7, ax, bx, ay, by, wf[4], wf[5]);
            mma8(tc4, tc5, tc6, tc7, az, bz, aw, bw, wf[6], wf[7]);
            float s_g  = fmaxf(tc0, 0.f) + fmaxf(tc1, 0.f)
                       + fmaxf(tc4, 0.f) + fmaxf(tc5, 0.f);
            float s_g8 = fmaxf(tc2, 0.f) + fmaxf(tc3, 0.f)
                       + fmaxf(tc6, 0.f) + fmaxf(tc7, 0.f);
            s_g  += __shfl_xor_sync(FULLMASK, s_g, 1);
            s_g  += __shfl_xor_sync(FULLMASK, s_g, 2);
            s_g8 += __shfl_xor_sync(FULLMASK, s_g8, 1);
            s_g8 += __shfl_xor_sync(FULLMASK, s_g8, 2);
            mub[rb][0] = Mmax * s_g;
            mub[rb][1] = Mmax * s_g8;
            daf[rb][0] = __float_as_uint(tc0); daf[rb][1] = __float_as_uint(tc2);
            daf[rb][2] = __float_as_uint(tc1); daf[rb][3] = __float_as_uint(tc3);
            dbf[rb][0] = __float_as_uint(tc4); dbf[rb][1] = __float_as_uint(tc6);
            dbf[rb][2] = __float_as_uint(tc5); dbf[rb][3] = __float_as_uint(tc7);
        }

        // ---- P2b: per j, one B-load feeds BOTH row-blocks ----
        float sg[2][2] = {{0.f, 0.f}, {0.f, 0.f}};
        float ae0[8], ae1[8];
#pragma unroll
        for (int i = 0; i < 8; ++i) { ae0[i] = 0.f; ae1[i] = 0.f; }

#pragma unroll
        for (int j = 0; j < 16; ++j) {
            float4 bv = *(const float4*)&ms1r_f[(8*j + g) * 16 + rot4];
            float2 e0v = *(const float2*)&ms1T_f[g       * 136 + j*8 + 2*tq];
            float2 e1v = *(const float2*)&ms1T_f[(8 + g) * 136 + j*8 + 2*tq];
            uint32_t bx = __float_as_uint(bv.x), by = __float_as_uint(bv.y);
            uint32_t bz = __float_as_uint(bv.z), bw = __float_as_uint(bv.w);
            uint32_t u0 = __float_as_uint(e0v.x), u1 = __float_as_uint(e0v.y);
            uint32_t u2 = __float_as_uint(e1v.x), u3 = __float_as_uint(e1v.y);
#pragma unroll
            for (int rb = 0; rb < 2; ++rb) {
                float c0 = -mub[rb][0], c1 = -mub[rb][0];
                float c2 = -mub[rb][1], c3 = -mub[rb][1];
                mma8(c0, c1, c2, c3, daf[rb][0], daf[rb][1], daf[rb][2],
                     daf[rb][3], bx, by);
                mma8(c0, c1, c2, c3, dbf[rb][0], dbf[rb][1], dbf[rb][2],
                     dbf[rb][3], bz, bw);
                float p0 = ex2(c0), p1 = ex2(c1), p2 = ex2(c2), p3 = ex2(c3);
                sg[rb][0] += p0 + p1; sg[rb][1] += p2 + p3;
                uint32_t a0 = __float_as_uint(p0);
                uint32_t a1 = __float_as_uint(p2);
                uint32_t a2 = __float_as_uint(p1);
                uint32_t a3 = __float_as_uint(p3);
                float* ae = rb ? ae1 : ae0;
                mma8(ae[0], ae[1], ae[2], ae[3], a0, a1, a2, a3, u0, u1);
                mma8(ae[4], ae[5], ae[6], ae[7], a0, a1, a2, a3, u2, u3);
            }
        }
        gbar(grp);   // B2a: tiles now dead; safe to overwrite with aeT
#pragma unroll
        for (int rb = 0; rb < 2; ++rb) {
            float s0 = sg[rb][0], s1 = sg[rb][1];
            s0 += __shfl_xor_sync(FULLMASK, s0, 1);
            s0 += __shfl_xor_sync(FULLMASK, s0, 2);
            s1 += __shfl_xor_sync(FULLMASK, s1, 1);
            s1 += __shfl_xor_sync(FULLMASK, s1, 2);
            const float inv0 = 1.f / s0, inv1 = 1.f / s1;
            const int R = gw * 32 + rb * 16;
            const float* ae = rb ? ae1 : ae0;
#pragma unroll
            for (int nt = 0; nt < 2; ++nt) {
                aeT[(8*nt + 2*tq)    *130 + R + g]     = ae[nt*4]   * inv0;
                aeT[(8*nt + 2*tq + 1)*130 + R + g]     = ae[nt*4+1] * inv0;
                aeT[(8*nt + 2*tq)    *130 + R + g + 8] = ae[nt*4+2] * inv1;
                aeT[(8*nt + 2*tq + 1)*130 + R + g + 8] = ae[nt*4+3] * inv1;
            }
        }
        gbar(grp);   // B2b

        // ---- P3: LayerNorm with edge fused into persistent registers ----
#pragma unroll
        for (int ei = 0; ei < 4; ++ei) {
            int e = gw * 4 + ei;
            float wa = w1a_all[h * 16 + e];
            float wb = w1b_all[h * 16 + e];
            float bi = b1s_all[h * 16 + e];
            float ewv = ews_all[h * 16 + e];
            float x[4];
#pragma unroll
            for (int ki = 0; ki < 4; ++ki) {
                int cc = l + 32 * ki;
                float ms = fmaxf(fmaf(scrow[cc], wa,
                                 fmaf(costrow[cc], wb, bi)), 0.f);
                x[ki] = aeT[e * 130 + cc] + ms;
            }
            float s1v = x[0] + x[1] + x[2] + x[3];
            float sq = x[0]*x[0] + x[1]*x[1] + x[2]*x[2] + x[3]*x[3];
#pragma unroll
            for (int o = 16; o; o >>= 1) {
                s1v += __shfl_xor_sync(FULLMASK, s1v, o);
                sq  += __shfl_xor_sync(FULLMASK, sq, o);
            }
            float mean = s1v * (1.f / 128.f);
            float var  = sq * (1.f / 128.f) - mean * mean;
            float rs = rsqrtf(var + 1e-5f);
#pragma unroll
            for (int ki = 0; ki < 4; ++ki) {
                int cc = l + 32 * ki;
                float val = (x[ki] - mean) * rs * lng[cc] + lnb[cc];
                eacc[ki] = fmaf(val, ewv, eacc[ki]);
            }
        }

        // ---- mixed softmax attention ----
        {
            float m0 = mixedrow[l],      m1 = mixedrow[l + 32];
            float m2 = mixedrow[l + 64], m3 = mixedrow[l + 96];
            float mx = fmaxf(fmaxf(m0, m1), fmaxf(m2, m3));
#pragma unroll
            for (int o = 16; o; o >>= 1) mx = fmaxf(mx, __shfl_xor_sync(FULLMASK, mx, o));
            float p0 = __expf(m0 - mx), p1 = __expf(m1 - mx);
            float p2 = __expf(m2 - mx), p3 = __expf(m3 - mx);
            float ssum = p0 + p1 + p2 + p3;
#pragma unroll
            for (int o = 16; o; o >>= 1) ssum += __shfl_xor_sync(FULLMASK, ssum, o);
            float inv = 1.f / ssum;
            const float* vb = v + (b * KH + h) * KC * KDQ;
#pragma unroll
            for (int d0 = 0; d0 < 4; ++d0) {
                int dq = gw * 4 + d0;
                float a = p0 * vb[l * 16 + dq] + p1 * vb[(l + 32) * 16 + dq]
                        + p2 * vb[(l + 64) * 16 + dq] + p3 * vb[(l + 96) * 16 + dq];
#pragma unroll
                for (int o = 16; o; o >>= 1) a += __shfl_xor_sync(FULLMASK, a, o);
                if (l == 0)
                    out[(b * KR + r) * (KH * KDQ) + h * KDQ + dq] = a * inv;
            }
        }
        gbar(grp);   // B3: aeT (aliased tiles) free for next-head P1
    }

    // ---- final edge reduce: stash per-warp partials, sum across 8 warps ----
    __syncthreads();
    float* ebuf = sm + 1040;   // group-0 region, dead now
    {
        const int w8 = tid >> 5;
#pragma unroll
        for (int ki = 0; ki < 4; ++ki)
            ebuf[w8 * 128 + l + 32 * ki] = eacc[ki];
    }
    __syncthreads();
    if (tid < 128) {
        float acc = edge_b[0];
#pragma unroll
        for (int w8 = 0; w8 < 8; ++w8) acc += ebuf[w8 * 128 + tid];
        out[KB * KR * KH * KDQ + br * 128 + tid] = acc;
    }
}

extern "C" void kernel_launch(void* const* d_in, const int* in_sizes, int n_in,
                              void* d_out, int out_size) {
    const float* q    = (const float*)d_in[0];
    const float* k_s  = (const float*)d_in[1];
    const float* k_a  = (const float*)d_in[2];
    const float* v    = (const float*)d_in[3];
    const float* cost = (const float*)d_in[4];
    const float* m1w  = (const float*)d_in[5];
    const float* m1b  = (const float*)d_in[6];
    const float* waa  = (const float*)d_in[7];
    const float* m2w  = (const float*)d_in[8];
    const float* m2b  = (const float*)d_in[9];
    const float* ew   = (const float*)d_in[10];
    const float* eb   = (const float*)d_in[11];
    const float* lng  = (const float*)d_in[12];
    const float* lnb  = (const float*)d_in[13];
    float* out = (float*)d_out;

    cudaFuncSetAttribute(k1_score, cudaFuncAttributeMaxDynamicSharedMemorySize, 111104);
    cudaFuncSetAttribute(k2_main,  cudaFuncAttributeMaxDynamicSharedMemorySize, 42688);

    k1_score<<<KB * KH * 4, 256, 111104>>>(q, k_s, k_a);
    k2_main<<<KB * KR, 256, 42688>>>(cost, m1w, m1b, waa, m2w, m2b, ew, eb,
                                     lng, lnb, v, out);
}